// round 1
// baseline (speedup 1.0000x reference)
#include <cuda_runtime.h>

#define Nn 50000
#define Ee 600000
#define Gg 512
#define Hh 128
#define OUTD 256

// ---------------- scratch (device globals: allocation-free) ----------------
__device__ float d_hA[Nn * Hh];
__device__ float d_hB[Nn * Hh];
__device__ float d_agg[Nn * Hh];
__device__ float d_pooled[Gg * 2 * Hh];
__device__ int   d_csr[Ee];
__device__ int   d_rowptr[Nn + 1];
__device__ int   d_cursor[Nn];
__device__ int   d_degi[Nn];
__device__ int   d_gcnt[Gg];
__device__ int   d_gptr[Gg + 1];
__device__ int   d_is64;

// ---------------- index dtype handling (int64 vs int32) ----------------
__device__ __forceinline__ int load_idx(const void* p, long long i, int is64) {
    if (is64) return (int)((const long long*)p)[i];
    return ((const int*)p)[i];
}

// If the underlying data is int32, reading it as int64 combines two random
// values in [0,50000) -> almost surely >= N or malformed. 64 samples => safe.
__global__ void detect_kernel(const void* __restrict__ ei) {
    const long long* p = (const long long*)ei;
    int ok = 1;
    for (int i = 0; i < 64; ++i) {
        long long v = p[i];
        if (v < 0 || v >= (long long)Nn) { ok = 0; break; }
    }
    d_is64 = ok;
}

__global__ void zero_kernel() {
    int i = blockIdx.x * blockDim.x + threadIdx.x;
    int stride = gridDim.x * blockDim.x;
    for (int j = i; j < Nn; j += stride) { d_degi[j] = 0; d_cursor[j] = 0; }
    for (int j = i; j < Gg; j += stride) d_gcnt[j] = 0;
}

// ---------------- CSR build ----------------
__global__ void deg_hist_kernel(const void* __restrict__ ei) {
    int is64 = d_is64;
    int stride = gridDim.x * blockDim.x;
    for (int e = blockIdx.x * blockDim.x + threadIdx.x; e < Ee; e += stride) {
        int dst = load_idx(ei, (long long)Ee + e, is64);
        atomicAdd(&d_degi[dst], 1);
    }
}

__global__ void batch_hist_kernel(const void* __restrict__ b) {
    int is64 = d_is64;
    int stride = gridDim.x * blockDim.x;
    for (int i = blockIdx.x * blockDim.x + threadIdx.x; i < Nn; i += stride) {
        int g = load_idx(b, i, is64);
        atomicAdd(&d_gcnt[g], 1);
    }
}

// Single-block exclusive scan; sel 0: degi->rowptr (n=Nn), sel 1: gcnt->gptr (n=Gg)
__global__ void scan_excl_kernel(int sel) {
    const int* in = sel ? d_gcnt : d_degi;
    int* out      = sel ? d_gptr : d_rowptr;
    int n         = sel ? Gg : Nn;
    __shared__ int sh[1024];
    int t = threadIdx.x;
    int run = 0;
    for (int base = 0; base < n; base += 1024) {
        int v = (base + t < n) ? in[base + t] : 0;
        sh[t] = v;
        __syncthreads();
        int x = v;
        for (int off = 1; off < 1024; off <<= 1) {
            int y = (t >= off) ? sh[t - off] : 0;
            __syncthreads();
            x += y;
            sh[t] = x;
            __syncthreads();
        }
        if (base + t < n) out[base + t] = run + x - v;
        run += sh[1023];
        __syncthreads();
    }
    if (t == 0) out[n] = run;
}

__global__ void csr_fill_kernel(const void* __restrict__ ei) {
    int is64 = d_is64;
    int stride = gridDim.x * blockDim.x;
    for (int e = blockIdx.x * blockDim.x + threadIdx.x; e < Ee; e += stride) {
        int src = load_idx(ei, e, is64);
        int dst = load_idx(ei, (long long)Ee + e, is64);
        int pos = d_rowptr[dst] + atomicAdd(&d_cursor[dst], 1);
        d_csr[pos] = src;
    }
}

// ---------------- mean aggregation: warp per node ----------------
// sel: 0 -> hx (external), 1 -> d_hA, 2 -> d_hB.  Output: d_agg.
__global__ void agg_kernel(const float* __restrict__ hx, int sel) {
    const float* h = (sel == 0) ? hx : (sel == 1 ? d_hA : d_hB);
    int warp = (blockIdx.x * blockDim.x + threadIdx.x) >> 5;
    int lane = threadIdx.x & 31;
    if (warp >= Nn) return;
    int beg = d_rowptr[warp];
    int end = d_rowptr[warp + 1];
    float4 acc = make_float4(0.f, 0.f, 0.f, 0.f);
    for (int e = beg; e < end; ++e) {
        int s = d_csr[e];
        float4 v = *reinterpret_cast<const float4*>(h + (long long)s * Hh + lane * 4);
        acc.x += v.x; acc.y += v.y; acc.z += v.z; acc.w += v.w;
    }
    int deg = end - beg;
    float inv = 1.f / (float)(deg > 1 ? deg : 1);
    acc.x *= inv; acc.y *= inv; acc.z *= inv; acc.w *= inv;
    *reinterpret_cast<float4*>(d_agg + (long long)warp * Hh + lane * 4) = acc;
}

// ---------------- fused dual SGEMM:  out = agg@W1^T + A2@W2^T + bias  ----------------
// A1 is always d_agg. a2sel: 0 -> xext, 1 -> d_hA, 2 -> d_hB.
// outsel: 1 -> d_hA, 2 -> d_hB.
__global__ __launch_bounds__(256) void sage_gemm_kernel(
    const float* __restrict__ xext, int a2sel, int outsel,
    const float* __restrict__ W1, const float* __restrict__ W2,
    const float* __restrict__ bias, int do_relu)
{
    const float* A2 = (a2sel == 0) ? xext : (a2sel == 1 ? d_hA : d_hB);
    float* out = (outsel == 1) ? d_hA : d_hB;

    __shared__ float Ast[16][132];   // [k][m], padded row (528B, 16B-aligned)
    __shared__ float Ws[16][128];    // [k][o]

    const int tid = threadIdx.x;
    const int tx = tid & 15;         // col group
    const int ty = tid >> 4;         // row group
    const int numTiles = (Nn + 127) / 128;

    for (int tile = blockIdx.x; tile < numTiles; tile += gridDim.x) {
        const int rowBase = tile * 128;
        float acc[8][8];
        #pragma unroll
        for (int m = 0; m < 8; m++)
            #pragma unroll
            for (int n = 0; n < 8; n++) acc[m][n] = 0.f;

        #pragma unroll
        for (int s = 0; s < 2; ++s) {
            const float* A = s ? A2 : d_agg;
            const float* W = s ? W2 : W1;
            #pragma unroll 1
            for (int kt = 0; kt < 128; kt += 16) {
                // A tile 128x16 -> Ast transposed
                #pragma unroll
                for (int i = 0; i < 2; ++i) {
                    int idx = tid + i * 256;       // 0..511
                    int r = idx >> 2, q = idx & 3;
                    int grow = rowBase + r;
                    float4 v = make_float4(0.f, 0.f, 0.f, 0.f);
                    if (grow < Nn)
                        v = *reinterpret_cast<const float4*>(A + (long long)grow * 128 + kt + q * 4);
                    Ast[q * 4 + 0][r] = v.x;
                    Ast[q * 4 + 1][r] = v.y;
                    Ast[q * 4 + 2][r] = v.z;
                    Ast[q * 4 + 3][r] = v.w;
                }
                // W tile: Ws[k][o] = W[o*128 + kt + k]
                #pragma unroll
                for (int i = 0; i < 2; ++i) {
                    int idx = tid + i * 256;
                    int o = idx >> 2, q = idx & 3;
                    float4 v = *reinterpret_cast<const float4*>(W + o * 128 + kt + q * 4);
                    Ws[q * 4 + 0][o] = v.x;
                    Ws[q * 4 + 1][o] = v.y;
                    Ws[q * 4 + 2][o] = v.z;
                    Ws[q * 4 + 3][o] = v.w;
                }
                __syncthreads();
                #pragma unroll
                for (int kk = 0; kk < 16; ++kk) {
                    float4 a0 = *reinterpret_cast<const float4*>(&Ast[kk][ty * 4]);
                    float4 a1 = *reinterpret_cast<const float4*>(&Ast[kk][64 + ty * 4]);
                    float4 b0 = *reinterpret_cast<const float4*>(&Ws[kk][tx * 4]);
                    float4 b1 = *reinterpret_cast<const float4*>(&Ws[kk][64 + tx * 4]);
                    float ar[8] = {a0.x, a0.y, a0.z, a0.w, a1.x, a1.y, a1.z, a1.w};
                    float br[8] = {b0.x, b0.y, b0.z, b0.w, b1.x, b1.y, b1.z, b1.w};
                    #pragma unroll
                    for (int m = 0; m < 8; m++)
                        #pragma unroll
                        for (int n = 0; n < 8; n++)
                            acc[m][n] = fmaf(ar[m], br[n], acc[m][n]);
                }
                __syncthreads();
            }
        }
        // epilogue: rows {ty*4+m, 64+ty*4+m}, cols {tx*4+n, 64+tx*4+n}
        #pragma unroll
        for (int m = 0; m < 8; m++) {
            int r = (m < 4) ? (ty * 4 + m) : (64 + ty * 4 + (m - 4));
            int grow = rowBase + r;
            if (grow >= Nn) continue;
            #pragma unroll
            for (int half = 0; half < 2; ++half) {
                int c0 = half ? (64 + tx * 4) : (tx * 4);
                int n0 = half * 4;
                float4 v;
                v.x = acc[m][n0 + 0] + bias[c0 + 0];
                v.y = acc[m][n0 + 1] + bias[c0 + 1];
                v.z = acc[m][n0 + 2] + bias[c0 + 2];
                v.w = acc[m][n0 + 3] + bias[c0 + 3];
                if (do_relu) {
                    v.x = fmaxf(v.x, 0.f); v.y = fmaxf(v.y, 0.f);
                    v.z = fmaxf(v.z, 0.f); v.w = fmaxf(v.w, 0.f);
                }
                *reinterpret_cast<float4*>(out + (long long)grow * 128 + c0) = v;
            }
        }
    }
}

// ---------------- global max/mean pool per graph ----------------
__global__ void pool_kernel() {
    int g = blockIdx.x;
    int c = threadIdx.x;              // 128 threads, one per column
    int beg = d_gptr[g], end = d_gptr[g + 1];
    float mx = -3.402823466e38f, sm = 0.f;
    for (int r = beg; r < end; ++r) {
        float v = d_hA[(long long)r * Hh + c];
        mx = fmaxf(mx, v);
        sm += v;
    }
    int cnt = end - beg;
    d_pooled[g * 256 + c]       = (cnt > 0) ? mx : 0.f;
    d_pooled[g * 256 + 128 + c] = sm / (float)(cnt > 1 ? cnt : 1);
}

// ---------------- head: out = pooled @ Wlin^T + blin ----------------
__global__ __launch_bounds__(256) void head_kernel(
    const float* __restrict__ Wlin, const float* __restrict__ blin,
    float* __restrict__ out)
{
    __shared__ float p[256];
    int g = blockIdx.x, o = threadIdx.x;
    p[o] = d_pooled[g * 256 + o];
    __syncthreads();
    float acc = blin[o];
    const float4* wr = reinterpret_cast<const float4*>(Wlin + o * 256);
    #pragma unroll 8
    for (int k = 0; k < 64; ++k) {
        float4 w = wr[k];
        float4 pv = *reinterpret_cast<const float4*>(&p[k * 4]);
        acc = fmaf(w.x, pv.x, acc);
        acc = fmaf(w.y, pv.y, acc);
        acc = fmaf(w.z, pv.z, acc);
        acc = fmaf(w.w, pv.w, acc);
    }
    out[g * 256 + o] = acc;
}

// ---------------- launch ----------------
extern "C" void kernel_launch(void* const* d_in, const int* in_sizes, int n_in,
                              void* d_out, int out_size)
{
    const float* x     = (const float*)d_in[0];
    const void*  ei    = d_in[1];
    const void*  batch = d_in[2];
    const float* W1l = (const float*)d_in[3];
    const float* b1  = (const float*)d_in[4];
    const float* W1r = (const float*)d_in[5];
    const float* W2l = (const float*)d_in[6];
    const float* b2  = (const float*)d_in[7];
    const float* W2r = (const float*)d_in[8];
    const float* W3l = (const float*)d_in[9];
    const float* b3  = (const float*)d_in[10];
    const float* W3r = (const float*)d_in[11];
    const float* Wlin = (const float*)d_in[12];
    const float* blin = (const float*)d_in[13];
    float* out = (float*)d_out;

    detect_kernel<<<1, 1>>>(ei);
    zero_kernel<<<128, 256>>>();
    deg_hist_kernel<<<1024, 256>>>(ei);
    batch_hist_kernel<<<256, 256>>>(batch);
    scan_excl_kernel<<<1, 1024>>>(0);
    scan_excl_kernel<<<1, 1024>>>(1);
    csr_fill_kernel<<<1024, 256>>>(ei);

    const int aggBlocks = (Nn * 32 + 255) / 256;   // warp per node
    const int gemmGrid = 296;                      // 2 CTAs/SM persistent

    // layer 1: relu(agg(x)@W1l^T + b1 + x@W1r^T) -> hA
    agg_kernel<<<aggBlocks, 256>>>(x, 0);
    sage_gemm_kernel<<<gemmGrid, 256>>>(x, 0, 1, W1l, W1r, b1, 1);
    // layer 2 -> hB
    agg_kernel<<<aggBlocks, 256>>>(nullptr, 1);
    sage_gemm_kernel<<<gemmGrid, 256>>>(nullptr, 1, 2, W2l, W2r, b2, 1);
    // layer 3 (no relu) -> hA
    agg_kernel<<<aggBlocks, 256>>>(nullptr, 2);
    sage_gemm_kernel<<<gemmGrid, 256>>>(nullptr, 2, 1, W3l, W3r, b3, 0);

    pool_kernel<<<Gg, 128>>>();
    head_kernel<<<Gg, 256>>>(Wlin, blin, out);
}

// round 4
// speedup vs baseline: 1.3393x; 1.3393x over previous
#include <cuda_runtime.h>
#include <cuda_bf16.h>
#include <cstdint>

#define Nn 50000
#define NnPad 50048
#define Ee 600000
#define Gg 512
#define NUM_TILES 391   // ceil(50000/128)

// ============================================================================
// PTX helpers: plain (non-'a') instructions only — ldmatrix / mma.sync / cp.async
// ============================================================================
__device__ __forceinline__ uint32_t smem_to_u32(const void* smem_ptr) {
    uint32_t addr;
    asm("{ .reg .u64 tmp; cvta.to.shared.u64 tmp, %1; cvt.u32.u64 %0, tmp; }"
        : "=r"(addr) : "l"(smem_ptr));
    return addr;
}

#define LDSM_X4(r0, r1, r2, r3, addr) \
    asm volatile("ldmatrix.sync.aligned.m8n8.x4.shared.b16 {%0,%1,%2,%3}, [%4];" \
        : "=r"(r0), "=r"(r1), "=r"(r2), "=r"(r3) : "r"(addr))

#define MMA16816(c, a0, a1, a2, a3, b0, b1) \
    asm volatile("mma.sync.aligned.m16n8k16.row.col.f32.bf16.bf16.f32 " \
        "{%0,%1,%2,%3}, {%4,%5,%6,%7}, {%8,%9}, {%0,%1,%2,%3};" \
        : "+f"((c)[0]), "+f"((c)[1]), "+f"((c)[2]), "+f"((c)[3]) \
        : "r"(a0), "r"(a1), "r"(a2), "r"(a3), "r"(b0), "r"(b1))

#define CP_ASYNC16(dst_u32, src_ptr) \
    asm volatile("cp.async.cg.shared.global [%0], [%1], 16;" \
        :: "r"(dst_u32), "l"(src_ptr) : "memory")
#define CP_COMMIT() asm volatile("cp.async.commit_group;" ::: "memory")
#define CP_WAIT1()  asm volatile("cp.async.wait_group 1;" ::: "memory")
#define CP_WAIT0()  asm volatile("cp.async.wait_group 0;" ::: "memory")

// ============================================================================
// Scratch (device globals: allocation-free)
// ============================================================================
__device__ __align__(16) __nv_bfloat16 d_Ahi[2][(size_t)NnPad * 256];
__device__ __align__(16) __nv_bfloat16 d_Alo[2][(size_t)NnPad * 256];
__device__ __align__(16) __nv_bfloat16 d_Wh[3 * 128 * 256];
__device__ __align__(16) __nv_bfloat16 d_Wl[3 * 128 * 256];
__device__ __align__(16) float d_h[(size_t)NnPad * 128];
__device__ float d_pooled[Gg * 256];
__device__ int   d_csr[Ee];
__device__ int   d_rowptr[Nn + 1];
__device__ int   d_cursor[Nn];
__device__ int   d_degi[Nn];
__device__ int   d_gptr[Gg + 1];
__device__ int   d_is64;

// ============================================================================
// index dtype handling (int64 vs int32)
// ============================================================================
__device__ __forceinline__ int load_idx(const void* p, long long i, int is64) {
    if (is64) return (int)((const long long*)p)[i];
    return ((const int*)p)[i];
}
__global__ void detect_kernel(const void* __restrict__ ei) {
    const long long* p = (const long long*)ei;
    int ok = 1;
    for (int i = 0; i < 64; ++i) {
        long long v = p[i];
        if (v < 0 || v >= (long long)Nn) { ok = 0; break; }
    }
    d_is64 = ok;
}

// gptr via binary search on sorted batch
__global__ void gptr_kernel(const void* __restrict__ batch) {
    int is64 = d_is64;
    int g = threadIdx.x;   // 0..511
    int lo = 0, hi = Nn;
    while (lo < hi) {
        int mid = (lo + hi) >> 1;
        int v = load_idx(batch, mid, is64);
        if (v < g) lo = mid + 1; else hi = mid;
    }
    d_gptr[g] = lo;
    if (g == 0) d_gptr[Gg] = Nn;
}

__global__ void zero_kernel() {
    int i = blockIdx.x * blockDim.x + threadIdx.x;
    int stride = gridDim.x * blockDim.x;
    for (int j = i; j < Nn; j += stride) { d_degi[j] = 0; d_cursor[j] = 0; }
}

__global__ void deg_hist_kernel(const void* __restrict__ ei) {
    int is64 = d_is64;
    int stride = gridDim.x * blockDim.x;
    for (int e = blockIdx.x * blockDim.x + threadIdx.x; e < Ee; e += stride) {
        int dst = load_idx(ei, (long long)Ee + e, is64);
        atomicAdd(&d_degi[dst], 1);
    }
}

// one-block segmented scan: degi -> rowptr (exclusive), rowptr[Nn] = total
__global__ void scan_kernel() {
    __shared__ int sh[1024];
    const int SEG = 49;   // 1024*49 = 50176 >= 50001
    int t = threadIdx.x;
    int base = t * SEG;
    int s = 0;
    #pragma unroll 7
    for (int i = 0; i < SEG; ++i) {
        int idx = base + i;
        if (idx < Nn) s += d_degi[idx];
    }
    sh[t] = s;
    __syncthreads();
    for (int off = 1; off < 1024; off <<= 1) {
        int v = (t >= off) ? sh[t - off] : 0;
        __syncthreads();
        sh[t] += v;
        __syncthreads();
    }
    int run = t ? sh[t - 1] : 0;
    #pragma unroll 7
    for (int i = 0; i < SEG; ++i) {
        int idx = base + i;
        if (idx < Nn) { d_rowptr[idx] = run; run += d_degi[idx]; }
        else if (idx == Nn) { d_rowptr[Nn] = run; }
    }
}

__global__ void csr_fill_kernel(const void* __restrict__ ei) {
    int is64 = d_is64;
    int stride = gridDim.x * blockDim.x;
    for (int e = blockIdx.x * blockDim.x + threadIdx.x; e < Ee; e += stride) {
        int src = load_idx(ei, e, is64);
        int dst = load_idx(ei, (long long)Ee + e, is64);
        int pos = d_rowptr[dst] + atomicAdd(&d_cursor[dst], 1);
        d_csr[pos] = src;
    }
}

// ============================================================================
// bf16 hi/lo split helpers
// ============================================================================
__device__ __forceinline__ void split_pack(float a, float b, uint32_t& hi, uint32_t& lo) {
    __nv_bfloat16 ha = __float2bfloat16_rn(a), hb = __float2bfloat16_rn(b);
    __nv_bfloat162 hv; hv.x = ha; hv.y = hb;
    hi = *reinterpret_cast<uint32_t*>(&hv);
    float la = a - __bfloat162float(ha);
    float lb = b - __bfloat162float(hb);
    __nv_bfloat162 lv = __floats2bfloat162_rn(la, lb);
    lo = *reinterpret_cast<uint32_t*>(&lv);
}

// convert weights: Wcat[layer][o][k] = k<128 ? Wl[o][k] : Wr[o][k-128], split hi/lo
__global__ void wprep_kernel(const float* W1l, const float* W1r,
                             const float* W2l, const float* W2r,
                             const float* W3l, const float* W3r) {
    int idx = blockIdx.x * blockDim.x + threadIdx.x;   // over 3*128*256
    if (idx >= 3 * 128 * 256) return;
    int layer = idx / (128 * 256);
    int rem = idx - layer * 128 * 256;
    int o = rem >> 8, k = rem & 255;
    const float* Wl = layer == 0 ? W1l : layer == 1 ? W2l : W3l;
    const float* Wr = layer == 0 ? W1r : layer == 1 ? W2r : W3r;
    float v = (k < 128) ? Wl[o * 128 + k] : Wr[o * 128 + k - 128];
    __nv_bfloat16 hv = __float2bfloat16_rn(v);
    float lvf = v - __bfloat162float(hv);
    d_Wh[idx] = hv;
    d_Wl[idx] = __float2bfloat16_rn(lvf);
}

// convert x into A buf[1], cols 128..255
__global__ void xconv_kernel(const float* __restrict__ x) {
    int idx = blockIdx.x * blockDim.x + threadIdx.x;   // Nn*32
    if (idx >= Nn * 32) return;
    int n = idx >> 5, c4 = idx & 31;
    float4 v = *reinterpret_cast<const float4*>(x + (size_t)n * 128 + c4 * 4);
    uint32_t h0, l0, h1, l1;
    split_pack(v.x, v.y, h0, l0);
    split_pack(v.z, v.w, h1, l1);
    size_t off = (size_t)n * 256 + 128 + c4 * 4;
    uint2 hh; hh.x = h0; hh.y = h1;
    uint2 ll; ll.x = l0; ll.y = l1;
    *reinterpret_cast<uint2*>(&d_Ahi[1][off]) = hh;
    *reinterpret_cast<uint2*>(&d_Alo[1][off]) = ll;
}

// ============================================================================
// mean aggregation: warp per node; writes bf16 hi/lo to A[outsel] cols 0..127
// ============================================================================
__global__ void agg_kernel(const float* __restrict__ x, int usex, int outsel) {
    const float* src = usex ? x : d_h;
    int warp = (blockIdx.x * blockDim.x + threadIdx.x) >> 5;
    int lane = threadIdx.x & 31;
    if (warp >= Nn) return;
    int beg = d_rowptr[warp];
    int end = d_rowptr[warp + 1];
    float4 acc = make_float4(0.f, 0.f, 0.f, 0.f);
    for (int e = beg; e < end; ++e) {
        int s = d_csr[e];
        float4 v = *reinterpret_cast<const float4*>(src + (size_t)s * 128 + lane * 4);
        acc.x += v.x; acc.y += v.y; acc.z += v.z; acc.w += v.w;
    }
    int deg = end - beg;
    float inv = 1.f / (float)(deg > 1 ? deg : 1);
    acc.x *= inv; acc.y *= inv; acc.z *= inv; acc.w *= inv;
    uint32_t h0, l0, h1, l1;
    split_pack(acc.x, acc.y, h0, l0);
    split_pack(acc.z, acc.w, h1, l1);
    size_t off = (size_t)warp * 256 + lane * 4;
    uint2 hh; hh.x = h0; hh.y = h1;
    uint2 ll; ll.x = l0; ll.y = l1;
    __nv_bfloat16* Ah = d_Ahi[outsel];
    __nv_bfloat16* Al = d_Alo[outsel];
    *reinterpret_cast<uint2*>(Ah + off) = hh;
    *reinterpret_cast<uint2*>(Al + off) = ll;
}

// ============================================================================
// Tensor-core GEMM via mma.sync (HMMA): h = relu?(A[bufsel] @ Wcat[layer]^T + b)
//   A: [NnPad, 256] split bf16 hi/lo.  W: [128, 256] split hi/lo (SMEM resident).
//   D = Ahi Whi + Ahi Wlo + Alo Whi, fp32 register accumulators.
//   Persistent CTAs; A streamed in 128x64 chunks via cp.async double buffer.
// SMEM: Whi 64KB | Wlo 64KB | Abuf 2x16KB | bias 512B  = 164352 B
// ============================================================================
#define OFF_WHI  0
#define OFF_WLO  65536
#define OFF_A    131072
#define OFF_BIAS 163840
#define GEMM_SMEM 164352

__device__ __forceinline__ void prefetch_chunk(const __nv_bfloat16* __restrict__ src,
                                               size_t rowBase, int cbase,
                                               uint32_t dst, int tid) {
    #pragma unroll
    for (int j = 0; j < 4; ++j) {
        int u = tid + j * 256;          // 0..1023 16B units
        int r = u >> 3, uu = u & 7;
        const __nv_bfloat16* s = src + (rowBase + r) * 256 + cbase + uu * 8;
        uint32_t d = dst + r * 128 + (((uu ^ (r & 7))) << 4);
        CP_ASYNC16(d, s);
    }
}

__global__ __launch_bounds__(256, 1)
void sage_mma_gemm(int bufsel, int nextsel, int layer,
                   const float* __restrict__ bias, int do_relu, int writeNext)
{
    extern __shared__ char smem[];
    const uint32_t sb = smem_to_u32(smem);
    const int tid = threadIdx.x;
    const int wid = tid >> 5, lane = tid & 31;

    const __nv_bfloat16* __restrict__ Ahi = d_Ahi[bufsel];
    const __nv_bfloat16* __restrict__ Alo = d_Alo[bufsel];
    const __nv_bfloat16* __restrict__ WhiG = d_Wh + layer * 32768;
    const __nv_bfloat16* __restrict__ WloG = d_Wl + layer * 32768;
    __nv_bfloat16* __restrict__ NAh = d_Ahi[nextsel];
    __nv_bfloat16* __restrict__ NAl = d_Alo[nextsel];
    float* sbias = reinterpret_cast<float*>(smem + OFF_BIAS);

    // ---- load W (hi+lo) into swizzled SMEM, once per CTA ----
    // W layer slab = 128 rows x 256 cols bf16 = 65536 B = 4096 16B-units.
    // 256 threads x 16 iterations covers exactly 4096 units.
    #pragma unroll
    for (int m = 0; m < 2; ++m) {
        const __nv_bfloat16* srcW = m ? WloG : WhiG;
        char* dstW = smem + (m ? OFF_WLO : OFF_WHI);
        #pragma unroll 4
        for (int j = 0; j < 16; ++j) {
            int idx = tid + j * 256;     // 0..4095 16B units
            int n = idx >> 5, u = idx & 31;   // n: 0..127 rows, u: 0..31 units/row
            float4 v = *reinterpret_cast<const float4*>(srcW + n * 256 + u * 8);
            *reinterpret_cast<float4*>(dstW + n * 512 + ((u ^ (n & 7)) << 4)) = v;
        }
    }
    if (tid < 128) sbias[tid] = bias[tid];
    __syncthreads();

    const uint32_t sA  = sb + OFF_A;
    const int wrow = wid * 16;

    for (int tile = blockIdx.x; tile < NUM_TILES; tile += gridDim.x) {
        const size_t rowBase = (size_t)tile * 128;

        float acc[64];
        #pragma unroll
        for (int i = 0; i < 64; ++i) acc[i] = 0.f;

        // chunk c: matrix = (c&1)?Alo:Ahi, k-base = (c>>1)*64, buf = c&1
        prefetch_chunk(Ahi, rowBase, 0, sA, tid);
        CP_COMMIT();

        #pragma unroll 1
        for (int c = 0; c < 8; ++c) {
            if (c < 7) {
                int cn = c + 1;
                prefetch_chunk((cn & 1) ? Alo : Ahi, rowBase, (cn >> 1) * 64,
                               sA + (cn & 1) * 16384, tid);
                CP_COMMIT();
                CP_WAIT1();
            } else {
                CP_WAIT0();
            }
            __syncthreads();

            const uint32_t abuf = sA + (c & 1) * 16384;
            const int cbase = (c >> 1) * 64;
            const int nW = (c & 1) ? 1 : 2;   // hi chunk hits Whi+Wlo; lo chunk hits Whi

            #pragma unroll
            for (int ks = 0; ks < 4; ++ks) {
                uint32_t a0, a1, a2, a3;
                {
                    int r = wrow + (lane & 15);
                    int u = ks * 2 + (lane >> 4);
                    uint32_t ad = abuf + r * 128 + (((u ^ (r & 7))) << 4);
                    LDSM_X4(a0, a1, a2, a3, ad);
                }
                #pragma unroll
                for (int w2 = 0; w2 < 2; ++w2) {
                    if (w2 >= nW) break;
                    const uint32_t sW = sb + (w2 ? OFF_WLO : OFF_WHI);
                    #pragma unroll
                    for (int ntp = 0; ntp < 8; ++ntp) {
                        int n = ntp * 16 + (lane & 15);
                        int kg = cbase + ks * 16 + ((lane >> 4) << 3);
                        int u = kg >> 3;
                        uint32_t bd = sW + n * 512 + (((u ^ (n & 7))) << 4);
                        uint32_t b0, b1, b2, b3;
                        LDSM_X4(b0, b1, b2, b3, bd);
                        MMA16816(&acc[(ntp * 2 + 0) * 4], a0, a1, a2, a3, b0, b2);
                        MMA16816(&acc[(ntp * 2 + 1) * 4], a0, a1, a2, a3, b1, b3);
                    }
                }
            }
            __syncthreads();
        }

        // ---- epilogue: bias + relu, fp32 out + bf16 split for next layer ----
        const int g = lane >> 2, tg = lane & 3;
        const int r0g = (int)rowBase + wrow + g;
        #pragma unroll
        for (int nt = 0; nt < 16; ++nt) {
            int col = nt * 8 + tg * 2;
            float2 bb = *reinterpret_cast<const float2*>(&sbias[col]);
            float v0 = acc[nt * 4 + 0] + bb.x;
            float v1 = acc[nt * 4 + 1] + bb.y;
            float v2 = acc[nt * 4 + 2] + bb.x;
            float v3 = acc[nt * 4 + 3] + bb.y;
            if (do_relu) {
                v0 = fmaxf(v0, 0.f); v1 = fmaxf(v1, 0.f);
                v2 = fmaxf(v2, 0.f); v3 = fmaxf(v3, 0.f);
            }
            if (r0g < Nn) {
                float2 o; o.x = v0; o.y = v1;
                *reinterpret_cast<float2*>(d_h + (size_t)r0g * 128 + col) = o;
                if (writeNext) {
                    uint32_t hh, ll;
                    split_pack(v0, v1, hh, ll);
                    size_t off = (size_t)r0g * 256 + 128 + col;
                    *reinterpret_cast<uint32_t*>(NAh + off) = hh;
                    *reinterpret_cast<uint32_t*>(NAl + off) = ll;
                }
            }
            if (r0g + 8 < Nn) {
                float2 o; o.x = v2; o.y = v3;
                *reinterpret_cast<float2*>(d_h + (size_t)(r0g + 8) * 128 + col) = o;
                if (writeNext) {
                    uint32_t hh, ll;
                    split_pack(v2, v3, hh, ll);
                    size_t off = (size_t)(r0g + 8) * 256 + 128 + col;
                    *reinterpret_cast<uint32_t*>(NAh + off) = hh;
                    *reinterpret_cast<uint32_t*>(NAl + off) = ll;
                }
            }
        }
        // no smem hazard: next iteration's first prefetch targets buf0,
        // whose last reads (chunk 6) completed before the chunk-7 __syncthreads
    }
}

// ============================================================================
// pooling + head
// ============================================================================
__global__ void pool_kernel() {
    int g = blockIdx.x;
    int c = threadIdx.x;              // 128 threads, one per column
    int beg = d_gptr[g], end = d_gptr[g + 1];
    float mx = -3.402823466e38f, sm = 0.f;
    for (int r = beg; r < end; ++r) {
        float v = d_h[(size_t)r * 128 + c];
        mx = fmaxf(mx, v);
        sm += v;
    }
    int cnt = end - beg;
    d_pooled[g * 256 + c]       = (cnt > 0) ? mx : 0.f;
    d_pooled[g * 256 + 128 + c] = sm / (float)(cnt > 1 ? cnt : 1);
}

__global__ __launch_bounds__(256) void head_kernel(
    const float* __restrict__ Wlin, const float* __restrict__ blin,
    float* __restrict__ out)
{
    __shared__ float p[256];
    int g = blockIdx.x, o = threadIdx.x;
    p[o] = d_pooled[g * 256 + o];
    __syncthreads();
    float acc = blin[o];
    const float4* wr = reinterpret_cast<const float4*>(Wlin + o * 256);
    #pragma unroll 8
    for (int k = 0; k < 64; ++k) {
        float4 w = wr[k];
        float4 pv = *reinterpret_cast<const float4*>(&p[k * 4]);
        acc = fmaf(w.x, pv.x, acc);
        acc = fmaf(w.y, pv.y, acc);
        acc = fmaf(w.z, pv.z, acc);
        acc = fmaf(w.w, pv.w, acc);
    }
    out[g * 256 + o] = acc;
}

// ============================================================================
// launch
// ============================================================================
extern "C" void kernel_launch(void* const* d_in, const int* in_sizes, int n_in,
                              void* d_out, int out_size)
{
    const float* x     = (const float*)d_in[0];
    const void*  ei    = d_in[1];
    const void*  batch = d_in[2];
    const float* W1l = (const float*)d_in[3];
    const float* b1  = (const float*)d_in[4];
    const float* W1r = (const float*)d_in[5];
    const float* W2l = (const float*)d_in[6];
    const float* b2  = (const float*)d_in[7];
    const float* W2r = (const float*)d_in[8];
    const float* W3l = (const float*)d_in[9];
    const float* b3  = (const float*)d_in[10];
    const float* W3r = (const float*)d_in[11];
    const float* Wlin = (const float*)d_in[12];
    const float* blin = (const float*)d_in[13];
    float* out = (float*)d_out;

    cudaFuncSetAttribute(sage_mma_gemm, cudaFuncAttributeMaxDynamicSharedMemorySize, GEMM_SMEM);

    detect_kernel<<<1, 1>>>(ei);
    gptr_kernel<<<1, 512>>>(batch);
    zero_kernel<<<98, 512>>>();
    deg_hist_kernel<<<512, 256>>>(ei);
    scan_kernel<<<1, 1024>>>();
    csr_fill_kernel<<<512, 256>>>(ei);

    wprep_kernel<<<384, 256>>>(W1l, W1r, W2l, W2r, W3l, W3r);
    xconv_kernel<<<6250, 256>>>(x);

    const int aggBlocks = (Nn * 32 + 255) / 256;   // warp per node

    // layer 1: reads A[1] (agg(x) | x), writes h1 + A[0] cols 128..255
    agg_kernel<<<aggBlocks, 256>>>(x, 1, 1);
    sage_mma_gemm<<<148, 256, GEMM_SMEM>>>(1, 0, 0, b1, 1, 1);
    // layer 2: reads A[0], writes h2 + A[1] cols 128..255
    agg_kernel<<<aggBlocks, 256>>>(nullptr, 0, 0);
    sage_mma_gemm<<<148, 256, GEMM_SMEM>>>(0, 1, 1, b2, 1, 1);
    // layer 3: reads A[1], writes h3 only
    agg_kernel<<<aggBlocks, 256>>>(nullptr, 0, 1);
    sage_mma_gemm<<<148, 256, GEMM_SMEM>>>(1, 0, 2, b3, 0, 0);

    pool_kernel<<<Gg, 128>>>();
    head_kernel<<<Gg, 256>>>(Wlin, blin, out);
}